// round 7
// baseline (speedup 1.0000x reference)
#include <cuda_runtime.h>

// QAEEncoder R7: warp-per-state, f32x2-packed, precomputed phase tables,
// XOR-swizzled unpadded staging (32KB/block -> 7 blocks/SM), launch_bounds(,7).
// Layouts over amp index i[9:0] (qubit q <-> bit p=9-q), amp (r,c)=(i[9:5],i[4:0]):
//   L1: lane=r, reg j=c        L0: lane=c, reg j=r
// Pipeline:
//   load+norm (L1, real, packed) -> A gates q9..5 (L1 reg bits, f32x2)
//   -> T_A (L1->L0) -> A gates q4..0 (L0) -> C1 gather+PhA (->L1 complex)
//   -> B gates q9..5 (L1) -> T_B (L1->L0) -> B gates q4..0
//   -> C2 gather+PhB (L0) -> packed expvals, stage-C RY folded; q6-9 traced out.
// CNOT-ring composite: new[i] = old[g(i)], g(i)=(i^(i>>1))^((i&1)?0x300:0).
// Staging swizzles (conflict <=2-way, verified per phase):
//   u64  amp (r,c): slot r*32 + (c^r)
//   f32  amp (r,c): float addr r*64 + ((c>>1)^(r&15))*2 + (c&1)

constexpr int SPB = 4;               // states (warps) per block
constexpr int NT  = 32 * SPB;
using u64 = unsigned long long;

__device__ float2 d_phA[1024];   // transposed: dest i at [(i&31)*32 + (i>>5)]
__device__ float2 d_phB[1024];   // natural:    dest i at [i]
__device__ float2 d_g[26];       // [0,20)=gAB half-angle, [20,26)=gC full-angle

__device__ __forceinline__ u64 pk2(float a, float b) {
    u64 r; asm("mov.b64 %0,{%1,%2};" : "=l"(r) : "f"(a), "f"(b)); return r;
}
__device__ __forceinline__ void upk2(u64 v, float& a, float& b) {
    asm("mov.b64 {%0,%1},%2;" : "=f"(a), "=f"(b) : "l"(v));
}
__device__ __forceinline__ u64 mul2(u64 a, u64 b) {
    u64 d; asm("mul.rn.f32x2 %0,%1,%2;" : "=l"(d) : "l"(a), "l"(b)); return d;
}
__device__ __forceinline__ u64 fma2(u64 a, u64 b, u64 c) {
    u64 d; asm("fma.rn.f32x2 %0,%1,%2,%3;" : "=l"(d) : "l"(a), "l"(b), "l"(c)); return d;
}
__device__ __forceinline__ float wsum(float v) {
#pragma unroll
    for (int o = 16; o; o >>= 1) v += __shfl_xor_sync(0xffffffffu, v, o);
    return v;
}
__device__ __forceinline__ int faddr(int r, int c) {           // float swizzle
    return r * 64 + (((c >> 1) ^ (r & 15)) << 1) + (c & 1);
}

// ---- setup: full phase tables + gate angles --------------------------------
__global__ void qae_setup(const float* __restrict__ w)
{
    int t = threadIdx.x;   // 1024 threads
    {
        int gi = (t ^ (t >> 1)) ^ ((t & 1) ? 0x300 : 0);
        float phA = 0.0f, phB = 0.0f;
#pragma unroll
        for (int p = 0; p < 10; p++) {
            float sgn = (gi >> p) & 1 ? 0.5f : -0.5f;
            phA += w[10 + 9 - p] * sgn;
            phB += w[40 + 9 - p] * sgn;
        }
        float c, s;
        sincosf(phA, &s, &c);
        d_phA[(t & 31) * 32 + (t >> 5)] = make_float2(c, s);
        sincosf(phB, &s, &c);
        d_phB[t] = make_float2(c, s);
    }
    if (t < 20) {
        int st = t / 10, q = t % 10;
        float th = st ? (w[20 + q] + w[30 + q]) : w[q];
        float c, s; sincosf(0.5f * th, &s, &c);
        d_g[t] = make_float2(c, s);
    } else if (t < 26) {
        float c, s; sincosf(w[50 + (t - 20)], &s, &c);
        d_g[t] = make_float2(c, s);
    }
}

__global__ void __launch_bounds__(NT, 7)
qae7_kernel(const float* __restrict__ x,
            float* __restrict__ out,
            int B, int D)
{
    __shared__ u64 sbuf[SPB][32 * 32];   // 32 KB total, XOR-swizzled staging

    const int tid  = threadIdx.x;
    const int wid  = tid >> 5;
    const int lane = tid & 31;
    const int b    = blockIdx.x * SPB + wid;
    if (b >= B) return;                 // warps fully independent (no block sync)

    u64*   bufu = sbuf[wid];
    float* bufr = (float*)bufu;

    // ---- load + normalize (L1, real, packed over c-bit0 = qubit-9 pairs) ---
    u64 PA[16];
    float ss = 0.0f;
    const float* xrow = x + (size_t)b * D + lane * 32;
#pragma unroll
    for (int t = 0; t < 8; t++) {
        int idx = lane * 32 + t * 4;
        float4 v;
        if (idx + 3 < D) {
            v = *(const float4*)(xrow + t * 4);
        } else {
            v.x = (idx     < D) ? xrow[t * 4]     : 0.0f;
            v.y = (idx + 1 < D) ? xrow[t * 4 + 1] : 0.0f;
            v.z = (idx + 2 < D) ? xrow[t * 4 + 2] : 0.0f;
            v.w = (idx + 3 < D) ? xrow[t * 4 + 3] : 0.0f;
        }
        PA[2 * t]     = pk2(v.x, v.y);
        PA[2 * t + 1] = pk2(v.z, v.w);
        ss += v.x * v.x + v.y * v.y + v.z * v.z + v.w * v.w;
    }
    ss = wsum(ss);
    float inv = 1.0f / fmaxf(sqrtf(ss), 1e-8f);
    {
        u64 invp = pk2(inv, inv);
#pragma unroll
        for (int k = 0; k < 16; k++) PA[k] = mul2(PA[k], invp);
    }

    // ---- stage A, qubits 9..5 (L1 reg bits; qubit 9 in-pack) ---------------
    {
        float2 g = __ldg(&d_g[9]);
        u64 cc = pk2(g.x, g.x), ns = pk2(-g.y, g.y);
#pragma unroll
        for (int k = 0; k < 16; k++) {
            u64 t = mul2(PA[k], cc);
            float lo, hi; upk2(PA[k], lo, hi);
            PA[k] = fma2(pk2(hi, lo), ns, t);
        }
    }
#pragma unroll
    for (int p = 1; p < 5; p++) {
        float2 g = __ldg(&d_g[9 - p]);
        u64 cc = pk2(g.x, g.x), sp = pk2(g.y, g.y), sn = pk2(-g.y, -g.y);
        int m = 1 << (p - 1);
#pragma unroll
        for (int k = 0; k < 16; k++) if (!(k & m)) {
            u64 a = PA[k], bb = PA[k | m];
            PA[k]     = fma2(bb, sn, mul2(a, cc));
            PA[k | m] = fma2(a, sp, mul2(bb, cc));
        }
    }

    // ---- T_A: L1 -> L0 (real, swizzled) ------------------------------------
#pragma unroll
    for (int k = 0; k < 16; k++)
        bufu[lane * 32 + (k ^ (lane & 15))] = PA[k];    // floats (lane, 2k/2k+1)
    __syncwarp();
    u64 PB[16];                         // L0, packed over r-bit0 = qubit-4 pairs
#pragma unroll
    for (int k = 0; k < 16; k++)
        PB[k] = pk2(bufr[faddr(2 * k, lane)], bufr[faddr(2 * k + 1, lane)]);
    __syncwarp();

    // ---- stage A, qubits 4..0 (L0 reg bits; qubit 4 in-pack) ---------------
    {
        float2 g = __ldg(&d_g[4]);
        u64 cc = pk2(g.x, g.x), ns = pk2(-g.y, g.y);
#pragma unroll
        for (int k = 0; k < 16; k++) {
            u64 t = mul2(PB[k], cc);
            float lo, hi; upk2(PB[k], lo, hi);
            PB[k] = fma2(pk2(hi, lo), ns, t);
        }
    }
#pragma unroll
    for (int p = 1; p < 5; p++) {
        float2 g = __ldg(&d_g[4 - p]);
        u64 cc = pk2(g.x, g.x), sp = pk2(g.y, g.y), sn = pk2(-g.y, -g.y);
        int m = 1 << (p - 1);
#pragma unroll
        for (int k = 0; k < 16; k++) if (!(k & m)) {
            u64 a = PB[k], bb = PB[k | m];
            PB[k]     = fma2(bb, sn, mul2(a, cc));
            PB[k | m] = fma2(a, sp, mul2(bb, cc));
        }
    }

    // ---- C1: CNOT gather + PhA (store L0, read into L1, -> complex) --------
    u64 P[32];
    {
#pragma unroll
        for (int k = 0; k < 16; k++) {
            float lo, hi; upk2(PB[k], lo, hi);
            bufr[faddr(2 * k,     lane)] = lo;
            bufr[faddr(2 * k + 1, lane)] = hi;
        }
        __syncwarp();
        const u64* phA = (const u64*)d_phA;
#pragma unroll
        for (int j = 0; j < 32; j++) {  // output L1: lane=i[9:5], j=i[4:0]
            int i  = (lane << 5) | j;
            int gi = (i ^ (i >> 1)) ^ ((j & 1) ? 0x300 : 0);
            float r = bufr[faddr(gi >> 5, gi & 31)];
            u64 ph = __ldg(&phA[j * 32 + lane]);   // transposed: coalesced
            P[j] = mul2(pk2(r, r), ph);
        }
        __syncwarp();
    }

    // ---- stage B, qubits 9..5 (L1 reg bits, complex f32x2) -----------------
#pragma unroll
    for (int bl = 0; bl < 5; bl++) {
        float2 g = __ldg(&d_g[10 + 9 - bl]);
        u64 cc = pk2(g.x, g.x), sp = pk2(g.y, g.y), sn = pk2(-g.y, -g.y);
        int m = 1 << bl;
#pragma unroll
        for (int j = 0; j < 32; j++) if (!(j & m)) {
            u64 a = P[j], bb = P[j | m];
            P[j]     = fma2(bb, sn, mul2(a, cc));
            P[j | m] = fma2(a, sp, mul2(bb, cc));
        }
    }

    // ---- T_B: L1 -> L0 (u64, swizzled) -------------------------------------
#pragma unroll
    for (int j = 0; j < 32; j++) bufu[lane * 32 + (j ^ lane)] = P[j];
    __syncwarp();
#pragma unroll
    for (int j = 0; j < 32; j++) P[j] = bufu[j * 32 + (lane ^ j)];
    __syncwarp();

    // ---- stage B, qubits 4..0 (L0 reg bits) --------------------------------
#pragma unroll
    for (int bl = 0; bl < 5; bl++) {
        float2 g = __ldg(&d_g[10 + 4 - bl]);
        u64 cc = pk2(g.x, g.x), sp = pk2(g.y, g.y), sn = pk2(-g.y, -g.y);
        int m = 1 << bl;
#pragma unroll
        for (int j = 0; j < 32; j++) if (!(j & m)) {
            u64 a = P[j], bb = P[j | m];
            P[j]     = fma2(bb, sn, mul2(a, cc));
            P[j | m] = fma2(a, sp, mul2(bb, cc));
        }
    }

    // ---- C2: CNOT gather + PhB (L0 -> L0, stay packed) ---------------------
    {
#pragma unroll
        for (int j = 0; j < 32; j++) bufu[j * 32 + (lane ^ j)] = P[j];
        __syncwarp();
        const u64* phB = (const u64*)d_phB;
#pragma unroll
        for (int j = 0; j < 32; j++) {  // output L0: lane=i[4:0], j=i[9:5]
            int i  = (j << 5) | lane;
            int gi = (i ^ (i >> 1)) ^ ((lane & 1) ? 0x300 : 0);
            u64 v = bufu[(gi >> 5) * 32 + ((gi & 31) ^ (gi >> 5))];
            u64 ph = __ldg(&phB[i]);                // natural: coalesced
            float vx, vy, pr, pi;
            upk2(v, vx, vy); upk2(ph, pr, pi);
            P[j] = pk2(vx * pr - vy * pi, vx * pi + vy * pr);
        }
    }

    // ---- Z expectations via partial Walsh tree (packed squares) ------------
    float zq[6];
    {
        float s0[16]; float z4 = 0.0f;
#pragma unroll
        for (int k = 0; k < 16; k++) {
            u64 sa = mul2(P[2 * k], P[2 * k]);
            u64 sb = mul2(P[2 * k + 1], P[2 * k + 1]);
            float al, ah, bl, bh; upk2(sa, al, ah); upk2(sb, bl, bh);
            float a = al + ah, bq = bl + bh;
            s0[k] = a + bq;  z4 += a - bq;
        }
        float s1[8]; float z3 = 0.0f;
#pragma unroll
        for (int k = 0; k < 8; k++) { s1[k] = s0[2 * k] + s0[2 * k + 1]; z3 += s0[2 * k] - s0[2 * k + 1]; }
        float s2[4]; float z2 = 0.0f;
#pragma unroll
        for (int k = 0; k < 4; k++) { s2[k] = s1[2 * k] + s1[2 * k + 1]; z2 += s1[2 * k] - s1[2 * k + 1]; }
        float s3[2]; float z1 = 0.0f;
#pragma unroll
        for (int k = 0; k < 2; k++) { s3[k] = s2[2 * k] + s2[2 * k + 1]; z1 += s2[2 * k] - s2[2 * k + 1]; }
        zq[0] = s3[0] - s3[1];
        zq[1] = z1; zq[2] = z2; zq[3] = z3; zq[4] = z4;
        float tot = s3[0] + s3[1];
        zq[5] = (lane & 16) ? -tot : tot;
    }

    // ---- X/Y expectations (packed accumulators) ----------------------------
    float xr[6], yi[6];
#pragma unroll
    for (int q = 0; q < 5; q++) {               // measured qubits 0..4 (j bits)
        int m = 1 << (4 - q);
        u64 acd = 0ull, acc = 0ull;
#pragma unroll
        for (int j = 0; j < 32; j++) if (!(j & m)) {
            u64 a = P[j], bp = P[j | m];
            acd = fma2(a, bp, acd);             // (Σ ax*bx, Σ ay*by)
            float bl, bh; upk2(bp, bl, bh);
            acc = fma2(a, pk2(bh, bl), acc);    // (Σ ax*by, Σ ay*bx)
        }
        float dl, dh, cl, ch; upk2(acd, dl, dh); upk2(acc, cl, ch);
        xr[q] = 2.0f * (dl + dh);
        yi[q] = 2.0f * (cl - ch);
    }
    {                                            // qubit 5 = lane bit 4
        u64 acd = 0ull, acc = 0ull;
#pragma unroll
        for (int j = 0; j < 32; j++) {
            u64 p = __shfl_xor_sync(0xffffffffu, P[j], 16);
            acd = fma2(P[j], p, acd);
            float pl, ph; upk2(p, pl, ph);
            acc = fma2(P[j], pk2(ph, pl), acc);
        }
        float dl, dh, cl, ch; upk2(acd, dl, dh); upk2(acc, cl, ch);
        float y5 = cl - ch;
        if (lane & 16) y5 = -y5;
        xr[5] = dl + dh;                         // counts both halves already
        yi[5] = y5;
    }

#pragma unroll
    for (int q = 0; q < 6; q++) {
        xr[q] = wsum(xr[q]);
        yi[q] = wsum(yi[q]);
        zq[q] = wsum(zq[q]);
    }

    if (lane == 0) {
        float* o = out + (size_t)b * 18;
#pragma unroll
        for (int q = 0; q < 6; q++) {
            float2 g = __ldg(&d_g[20 + q]);
            o[q]      = g.x * xr[q] + g.y * zq[q];
            o[6 + q]  = yi[q];
            o[12 + q] = g.x * zq[q] - g.y * xr[q];
        }
    }
}

extern "C" void kernel_launch(void* const* d_in, const int* in_sizes, int n_in,
                              void* d_out, int out_size)
{
    int ix = 0, iw = 1;
    if (n_in >= 2 && in_sizes[0] < in_sizes[1]) { ix = 1; iw = 0; }
    const float* x = (const float*)d_in[ix];
    const float* w = (const float*)d_in[iw];
    float* out = (float*)d_out;

    int B = out_size / 18;
    int D = (B > 0) ? (in_sizes[ix] / B) : 0;

    qae_setup<<<1, 1024>>>(w);
    int grid = (B + SPB - 1) / SPB;
    qae7_kernel<<<grid, NT>>>(x, out, B, D);
}

// round 8
// speedup vs baseline: 1.1193x; 1.1193x over previous
#include <cuda_runtime.h>

// QAEEncoder R8: warp-per-state, f32x2-packed, precomputed phase tables,
// XOR-swizzled 32KB staging, warps independent, launch_bounds(128,6) (no spills).
// Layouts over amp index i[9:0] (qubit q <-> bit p=9-q), amp (r,c)=(i[9:5],i[4:0]):
//   L1: lane=r, reg j=c        L0: lane=c, reg j=r
// Pipeline:
//   load+norm (L1, real, packed; norm folded into first gate)
//   -> A gates q9..5 (L1 reg bits, f32x2) -> T_A (L1->L0) -> A gates q4..0 (L0)
//   -> C1 gather+PhA (->L1 complex) -> B gates q9..5 (L1) -> T_B (L1->L0)
//   -> B gates q4..0 (L0) -> C2 gather+PhB -> packed expvals, stage-C RY folded;
//   qubits 6-9 traced out (cannot affect measured reduced state).
// CNOT-ring composite: new[i] = old[g(i)], g(i)=(i^(i>>1))^((i&1)?0x300:0).
// Staging swizzles (<=2-way conflicts, bench-verified in R7):
//   u64  amp (r,c): slot r*32 + (c^r)
//   f32  amp (r,c): float addr r*64 + ((c>>1)^(r&15))*2 + (c&1)

constexpr int SPB = 4;               // states (warps) per block
constexpr int NT  = 32 * SPB;
using u64 = unsigned long long;

__device__ float2 d_phA[1024];   // transposed: dest i at [(i&31)*32 + (i>>5)]
__device__ float2 d_phB[1024];   // natural:    dest i at [i]
__device__ float2 d_g[26];       // [0,20)=gAB half-angle, [20,26)=gC full-angle

__device__ __forceinline__ u64 pk2(float a, float b) {
    u64 r; asm("mov.b64 %0,{%1,%2};" : "=l"(r) : "f"(a), "f"(b)); return r;
}
__device__ __forceinline__ void upk2(u64 v, float& a, float& b) {
    asm("mov.b64 {%0,%1},%2;" : "=f"(a), "=f"(b) : "l"(v));
}
__device__ __forceinline__ u64 mul2(u64 a, u64 b) {
    u64 d; asm("mul.rn.f32x2 %0,%1,%2;" : "=l"(d) : "l"(a), "l"(b)); return d;
}
__device__ __forceinline__ u64 fma2(u64 a, u64 b, u64 c) {
    u64 d; asm("fma.rn.f32x2 %0,%1,%2,%3;" : "=l"(d) : "l"(a), "l"(b), "l"(c)); return d;
}
__device__ __forceinline__ float wsum(float v) {
#pragma unroll
    for (int o = 16; o; o >>= 1) v += __shfl_xor_sync(0xffffffffu, v, o);
    return v;
}
__device__ __forceinline__ int faddr(int r, int c) {           // float swizzle
    return r * 64 + (((c >> 1) ^ (r & 15)) << 1) + (c & 1);
}

// ---- setup: full phase tables + gate angles --------------------------------
__global__ void qae_setup(const float* __restrict__ w)
{
    int t = threadIdx.x;   // 1024 threads
    {
        int gi = (t ^ (t >> 1)) ^ ((t & 1) ? 0x300 : 0);
        float phA = 0.0f, phB = 0.0f;
#pragma unroll
        for (int p = 0; p < 10; p++) {
            float sgn = (gi >> p) & 1 ? 0.5f : -0.5f;
            phA += w[10 + 9 - p] * sgn;
            phB += w[40 + 9 - p] * sgn;
        }
        float c, s;
        sincosf(phA, &s, &c);
        d_phA[(t & 31) * 32 + (t >> 5)] = make_float2(c, s);
        sincosf(phB, &s, &c);
        d_phB[t] = make_float2(c, s);
    }
    if (t < 20) {
        int st = t / 10, q = t % 10;
        float th = st ? (w[20 + q] + w[30 + q]) : w[q];
        float c, s; sincosf(0.5f * th, &s, &c);
        d_g[t] = make_float2(c, s);
    } else if (t < 26) {
        float c, s; sincosf(w[50 + (t - 20)], &s, &c);
        d_g[t] = make_float2(c, s);
    }
}

__global__ void __launch_bounds__(NT, 6)
qae8_kernel(const float* __restrict__ x,
            float* __restrict__ out,
            int B, int D)
{
    __shared__ u64 sbuf[SPB][32 * 32];   // 32 KB total, XOR-swizzled staging

    const int tid  = threadIdx.x;
    const int wid  = tid >> 5;
    const int lane = tid & 31;
    const int b    = blockIdx.x * SPB + wid;
    if (b >= B) return;                 // warps fully independent

    u64*   bufu = sbuf[wid];
    float* bufr = (float*)bufu;

    // ---- load (L1, real, packed over c-bit0 = qubit-9 pairs) ---------------
    u64 PA[16];
    float ss = 0.0f;
    const float* xrow = x + (size_t)b * D + lane * 32;
    if ((lane + 1) * 32 <= D) {         // fast path: row fully in-bounds
#pragma unroll
        for (int t = 0; t < 8; t++) {
            float4 v = *(const float4*)(xrow + t * 4);
            PA[2 * t]     = pk2(v.x, v.y);
            PA[2 * t + 1] = pk2(v.z, v.w);
            ss += v.x * v.x + v.y * v.y + v.z * v.z + v.w * v.w;
        }
    } else {
#pragma unroll
        for (int t = 0; t < 8; t++) {
            int idx = lane * 32 + t * 4;
            float4 v;
            v.x = (idx     < D) ? xrow[t * 4]     : 0.0f;
            v.y = (idx + 1 < D) ? xrow[t * 4 + 1] : 0.0f;
            v.z = (idx + 2 < D) ? xrow[t * 4 + 2] : 0.0f;
            v.w = (idx + 3 < D) ? xrow[t * 4 + 3] : 0.0f;
            PA[2 * t]     = pk2(v.x, v.y);
            PA[2 * t + 1] = pk2(v.z, v.w);
            ss += v.x * v.x + v.y * v.y + v.z * v.z + v.w * v.w;
        }
    }
    ss = wsum(ss);
    float inv = 1.0f / fmaxf(sqrtf(ss), 1e-8f);

    // ---- stage A, qubits 9..5 (L1 reg bits; qubit 9 in-pack, norm folded) --
    {
        float2 g = __ldg(&d_g[9]);
        float ci = g.x * inv, si = g.y * inv;           // fold 1/norm into gate
        u64 cc = pk2(ci, ci), ns = pk2(-si, si);
#pragma unroll
        for (int k = 0; k < 16; k++) {
            u64 t = mul2(PA[k], cc);
            float lo, hi; upk2(PA[k], lo, hi);
            PA[k] = fma2(pk2(hi, lo), ns, t);
        }
    }
#pragma unroll
    for (int p = 1; p < 5; p++) {
        float2 g = __ldg(&d_g[9 - p]);
        u64 cc = pk2(g.x, g.x), sp = pk2(g.y, g.y), sn = pk2(-g.y, -g.y);
        int m = 1 << (p - 1);
#pragma unroll
        for (int k = 0; k < 16; k++) if (!(k & m)) {
            u64 a = PA[k], bb = PA[k | m];
            PA[k]     = fma2(bb, sn, mul2(a, cc));
            PA[k | m] = fma2(a, sp, mul2(bb, cc));
        }
    }

    // ---- T_A: L1 -> L0 (real, swizzled) ------------------------------------
#pragma unroll
    for (int k = 0; k < 16; k++)
        bufu[lane * 32 + (k ^ (lane & 15))] = PA[k];    // floats (lane, 2k/2k+1)
    __syncwarp();
    u64 PB[16];                         // L0, packed over r-bit0 = qubit-4 pairs
#pragma unroll
    for (int k = 0; k < 16; k++)
        PB[k] = pk2(bufr[faddr(2 * k, lane)], bufr[faddr(2 * k + 1, lane)]);
    __syncwarp();

    // ---- stage A, qubits 4..0 (L0 reg bits; qubit 4 in-pack) ---------------
    {
        float2 g = __ldg(&d_g[4]);
        u64 cc = pk2(g.x, g.x), ns = pk2(-g.y, g.y);
#pragma unroll
        for (int k = 0; k < 16; k++) {
            u64 t = mul2(PB[k], cc);
            float lo, hi; upk2(PB[k], lo, hi);
            PB[k] = fma2(pk2(hi, lo), ns, t);
        }
    }
#pragma unroll
    for (int p = 1; p < 5; p++) {
        float2 g = __ldg(&d_g[4 - p]);
        u64 cc = pk2(g.x, g.x), sp = pk2(g.y, g.y), sn = pk2(-g.y, -g.y);
        int m = 1 << (p - 1);
#pragma unroll
        for (int k = 0; k < 16; k++) if (!(k & m)) {
            u64 a = PB[k], bb = PB[k | m];
            PB[k]     = fma2(bb, sn, mul2(a, cc));
            PB[k | m] = fma2(a, sp, mul2(bb, cc));
        }
    }

    // ---- C1: CNOT gather + PhA (store L0, read into L1, -> complex) --------
    u64 P[32];
    {
#pragma unroll
        for (int k = 0; k < 16; k++) {
            float lo, hi; upk2(PB[k], lo, hi);
            bufr[faddr(2 * k,     lane)] = lo;
            bufr[faddr(2 * k + 1, lane)] = hi;
        }
        __syncwarp();
        const u64* phA = (const u64*)d_phA;
#pragma unroll
        for (int j = 0; j < 32; j++) {  // output L1: lane=i[9:5], j=i[4:0]
            int i  = (lane << 5) | j;
            int gi = (i ^ (i >> 1)) ^ ((j & 1) ? 0x300 : 0);
            float r = bufr[faddr(gi >> 5, gi & 31)];
            u64 ph = __ldg(&phA[j * 32 + lane]);   // transposed: coalesced
            P[j] = mul2(pk2(r, r), ph);
        }
        __syncwarp();
    }

    // ---- stage B, qubits 9..5 (L1 reg bits, complex f32x2) -----------------
#pragma unroll
    for (int bl = 0; bl < 5; bl++) {
        float2 g = __ldg(&d_g[10 + 9 - bl]);
        u64 cc = pk2(g.x, g.x), sp = pk2(g.y, g.y), sn = pk2(-g.y, -g.y);
        int m = 1 << bl;
#pragma unroll
        for (int j = 0; j < 32; j++) if (!(j & m)) {
            u64 a = P[j], bb = P[j | m];
            P[j]     = fma2(bb, sn, mul2(a, cc));
            P[j | m] = fma2(a, sp, mul2(bb, cc));
        }
    }

    // ---- T_B: L1 -> L0 (u64, swizzled) -------------------------------------
#pragma unroll
    for (int j = 0; j < 32; j++) bufu[lane * 32 + (j ^ lane)] = P[j];
    __syncwarp();
#pragma unroll
    for (int j = 0; j < 32; j++) P[j] = bufu[j * 32 + (lane ^ j)];
    __syncwarp();

    // ---- stage B, qubits 4..0 (L0 reg bits) --------------------------------
#pragma unroll
    for (int bl = 0; bl < 5; bl++) {
        float2 g = __ldg(&d_g[10 + 4 - bl]);
        u64 cc = pk2(g.x, g.x), sp = pk2(g.y, g.y), sn = pk2(-g.y, -g.y);
        int m = 1 << bl;
#pragma unroll
        for (int j = 0; j < 32; j++) if (!(j & m)) {
            u64 a = P[j], bb = P[j | m];
            P[j]     = fma2(bb, sn, mul2(a, cc));
            P[j | m] = fma2(a, sp, mul2(bb, cc));
        }
    }

    // ---- C2: CNOT gather + PhB (L0 -> L0, stay packed) ---------------------
    {
#pragma unroll
        for (int j = 0; j < 32; j++) bufu[j * 32 + (lane ^ j)] = P[j];
        __syncwarp();
        const u64* phB = (const u64*)d_phB;
#pragma unroll
        for (int j = 0; j < 32; j++) {  // output L0: lane=i[4:0], j=i[9:5]
            int i  = (j << 5) | lane;
            int gi = (i ^ (i >> 1)) ^ ((lane & 1) ? 0x300 : 0);
            u64 v = bufu[(gi >> 5) * 32 + ((gi & 31) ^ (gi >> 5))];
            u64 ph = __ldg(&phB[i]);                // natural: coalesced
            float vx, vy, pr, pi;
            upk2(v, vx, vy); upk2(ph, pr, pi);
            P[j] = pk2(vx * pr - vy * pi, vx * pi + vy * pr);
        }
    }

    // ---- Z expectations via partial Walsh tree (packed squares) ------------
    float zq[6];
    {
        float s0[16]; float z4 = 0.0f;
#pragma unroll
        for (int k = 0; k < 16; k++) {
            u64 sa = mul2(P[2 * k], P[2 * k]);
            u64 sb = mul2(P[2 * k + 1], P[2 * k + 1]);
            float al, ah, bl, bh; upk2(sa, al, ah); upk2(sb, bl, bh);
            float a = al + ah, bq = bl + bh;
            s0[k] = a + bq;  z4 += a - bq;
        }
        float s1[8]; float z3 = 0.0f;
#pragma unroll
        for (int k = 0; k < 8; k++) { s1[k] = s0[2 * k] + s0[2 * k + 1]; z3 += s0[2 * k] - s0[2 * k + 1]; }
        float s2[4]; float z2 = 0.0f;
#pragma unroll
        for (int k = 0; k < 4; k++) { s2[k] = s1[2 * k] + s1[2 * k + 1]; z2 += s1[2 * k] - s1[2 * k + 1]; }
        float s3[2]; float z1 = 0.0f;
#pragma unroll
        for (int k = 0; k < 2; k++) { s3[k] = s2[2 * k] + s2[2 * k + 1]; z1 += s2[2 * k] - s2[2 * k + 1]; }
        zq[0] = s3[0] - s3[1];
        zq[1] = z1; zq[2] = z2; zq[3] = z3; zq[4] = z4;
        float tot = s3[0] + s3[1];
        zq[5] = (lane & 16) ? -tot : tot;
    }

    // ---- X/Y expectations (packed accumulators) ----------------------------
    float xr[6], yi[6];
#pragma unroll
    for (int q = 0; q < 5; q++) {               // measured qubits 0..4 (j bits)
        int m = 1 << (4 - q);
        u64 acd = 0ull, acc = 0ull;
#pragma unroll
        for (int j = 0; j < 32; j++) if (!(j & m)) {
            u64 a = P[j], bp = P[j | m];
            acd = fma2(a, bp, acd);             // (Σ ax*bx, Σ ay*by)
            float bl, bh; upk2(bp, bl, bh);
            acc = fma2(a, pk2(bh, bl), acc);    // (Σ ax*by, Σ ay*bx)
        }
        float dl, dh, cl, ch; upk2(acd, dl, dh); upk2(acc, cl, ch);
        xr[q] = 2.0f * (dl + dh);
        yi[q] = 2.0f * (cl - ch);
    }
    {                                            // qubit 5 = lane bit 4
        u64 acd = 0ull, acc = 0ull;
#pragma unroll
        for (int j = 0; j < 32; j++) {
            u64 p = __shfl_xor_sync(0xffffffffu, P[j], 16);
            acd = fma2(P[j], p, acd);
            float pl, ph; upk2(p, pl, ph);
            acc = fma2(P[j], pk2(ph, pl), acc);
        }
        float dl, dh, cl, ch; upk2(acd, dl, dh); upk2(acc, cl, ch);
        float y5 = cl - ch;
        if (lane & 16) y5 = -y5;
        xr[5] = dl + dh;                         // counts both halves already
        yi[5] = y5;
    }

#pragma unroll
    for (int q = 0; q < 6; q++) {
        xr[q] = wsum(xr[q]);
        yi[q] = wsum(yi[q]);
        zq[q] = wsum(zq[q]);
    }

    if (lane == 0) {
        float* o = out + (size_t)b * 18;
#pragma unroll
        for (int q = 0; q < 6; q++) {
            float2 g = __ldg(&d_g[20 + q]);
            o[q]      = g.x * xr[q] + g.y * zq[q];
            o[6 + q]  = yi[q];
            o[12 + q] = g.x * zq[q] - g.y * xr[q];
        }
    }
}

extern "C" void kernel_launch(void* const* d_in, const int* in_sizes, int n_in,
                              void* d_out, int out_size)
{
    int ix = 0, iw = 1;
    if (n_in >= 2 && in_sizes[0] < in_sizes[1]) { ix = 1; iw = 0; }
    const float* x = (const float*)d_in[ix];
    const float* w = (const float*)d_in[iw];
    float* out = (float*)d_out;

    int B = out_size / 18;
    int D = (B > 0) ? (in_sizes[ix] / B) : 0;

    qae_setup<<<1, 1024>>>(w);
    int grid = (B + SPB - 1) / SPB;
    qae8_kernel<<<grid, NT>>>(x, out, B, D);
}

// round 9
// speedup vs baseline: 1.3155x; 1.1752x over previous
#include <cuda_runtime.h>

// QAEEncoder R9: 2 warps per state (64-thread block = 1 state), 16 amps/thread.
// Amp index i[9:0], qubit q <-> bit p=9-q.
// Layout LA : thread t = i[9:4]  (w=i9, lane=i[8:4]), reg ra = i[3:0].
//             real pack over i0 (q9). Load is 16 consecutive floats -> float4s.
// Layout LB': i = rb*64 + lane*2 + w  (w=i0=q9 unmeasured; lane=i[5:1]; rb=i[9:6]).
//             real pack over i6 (q3).
// Gates: LA covers q9..q6 (reg) + q5,q4 (shfl xor 1,2); LB' covers q3..q0 (reg).
// Stage A real packed -> T1 -> LB' gates -> C1 gather+PhA (complex, into LA)
// -> stage B LA (reg+shfl) -> T2 -> LB' gates -> C2 gather+PhB (LB')
// -> expvals (q0-q3 reg, q5 shfl8, q4 shfl16), stage-C RY folded; q6-9 traced.
// CNOT-ring composite: new[i] = old[g(i)], g(i)=(i^(i>>1))^((i&1)?0x300:0).
// Shared staging: padded addr(i) = i + (i>>5)  (float or u64 units).

constexpr int NT = 64;
using u64 = unsigned long long;

__device__ float2 d_phA[1024];   // C1 reader order: [ra*64 + t]
__device__ float2 d_phB[1024];   // C2 reader order: [rb*64 + t]
__device__ float2 d_g[26];       // [0,20)=gAB half-angle, [20,26)=gC full-angle

__device__ __forceinline__ u64 pk2(float a, float b) {
    u64 r; asm("mov.b64 %0,{%1,%2};" : "=l"(r) : "f"(a), "f"(b)); return r;
}
__device__ __forceinline__ void upk2(u64 v, float& a, float& b) {
    asm("mov.b64 {%0,%1},%2;" : "=f"(a), "=f"(b) : "l"(v));
}
__device__ __forceinline__ u64 mul2(u64 a, u64 b) {
    u64 d; asm("mul.rn.f32x2 %0,%1,%2;" : "=l"(d) : "l"(a), "l"(b)); return d;
}
__device__ __forceinline__ u64 fma2(u64 a, u64 b, u64 c) {
    u64 d; asm("fma.rn.f32x2 %0,%1,%2,%3;" : "=l"(d) : "l"(a), "l"(b), "l"(c)); return d;
}
__device__ __forceinline__ float wsum(float v) {
#pragma unroll
    for (int o = 16; o; o >>= 1) v += __shfl_xor_sync(0xffffffffu, v, o);
    return v;
}

// ---- setup ------------------------------------------------------------------
__global__ void qae_setup(const float* __restrict__ w)
{
    int u = threadIdx.x;                 // 1024 threads
    int t = u & 63, rr = u >> 6;
    {   // phA: C1 output amp (LA): i = t*16 + ra,  ra = rr
        int i  = t * 16 + rr;
        int gi = (i ^ (i >> 1)) ^ ((i & 1) ? 0x300 : 0);
        float ph = 0.0f;
#pragma unroll
        for (int p = 0; p < 10; p++)
            ph += w[10 + 9 - p] * (((gi >> p) & 1) ? 0.5f : -0.5f);
        float c, s; sincosf(ph, &s, &c);
        d_phA[u] = make_float2(c, s);
    }
    {   // phB: C2 output amp (LB'): i = rb*64 + lane*2 + w,  rb = rr
        int i  = rr * 64 + (t & 31) * 2 + (t >> 5);
        int gi = (i ^ (i >> 1)) ^ ((i & 1) ? 0x300 : 0);
        float ph = 0.0f;
#pragma unroll
        for (int p = 0; p < 10; p++)
            ph += w[40 + 9 - p] * (((gi >> p) & 1) ? 0.5f : -0.5f);
        float c, s; sincosf(ph, &s, &c);
        d_phB[u] = make_float2(c, s);
    }
    if (u < 20) {
        int st = u / 10, q = u % 10;
        float th = st ? (w[20 + q] + w[30 + q]) : w[q];
        float c, s; sincosf(0.5f * th, &s, &c);
        d_g[u] = make_float2(c, s);
    } else if (u < 26) {
        float c, s; sincosf(w[50 + (u - 20)], &s, &c);
        d_g[u] = make_float2(c, s);
    }
}

__global__ void __launch_bounds__(NT, 14)
qae9_kernel(const float* __restrict__ x,
            float* __restrict__ out,
            int B, int D)
{
    __shared__ u64    sbuf[1056];        // 8448 B staging: addr(i)=i+(i>>5)
    __shared__ float2 sg[26];
    __shared__ float  sred[2];
    __shared__ float  sacc[36];

    const int t    = threadIdx.x;
    const int w    = t >> 5;
    const int lane = t & 31;
    const int b    = blockIdx.x;

    if (t < 26) sg[t] = d_g[t];

    float* bufr = (float*)sbuf;
    u64*   bufu = sbuf;

    // ---- load (LA: 16 consecutive amps/thread) + squared norm --------------
    u64 PA[8];
    float ss = 0.0f;
    if ((t + 1) * 16 <= D) {
        const float4* xr4 = (const float4*)(x + (size_t)b * D + t * 16);
#pragma unroll
        for (int k = 0; k < 4; k++) {
            float4 v = xr4[k];
            PA[2 * k]     = pk2(v.x, v.y);
            PA[2 * k + 1] = pk2(v.z, v.w);
            ss += v.x * v.x + v.y * v.y + v.z * v.z + v.w * v.w;
        }
    } else {
        const float* xrow = x + (size_t)b * D;
#pragma unroll
        for (int k = 0; k < 8; k++) {
            int i0 = t * 16 + 2 * k;
            float lo = (i0     < D) ? xrow[i0]     : 0.0f;
            float hi = (i0 + 1 < D) ? xrow[i0 + 1] : 0.0f;
            PA[k] = pk2(lo, hi);
            ss += lo * lo + hi * hi;
        }
    }
    ss = wsum(ss);
    if (lane == 0) sred[w] = ss;
    __syncthreads();
    float inv = 1.0f / fmaxf(sqrtf(sred[0] + sred[1]), 1e-8f);

    // ---- stage A in LA: q9 in-pack (norm folded), q8..q6 pack-pairs --------
    {
        float2 g = sg[9];
        float ci = g.x * inv, si = g.y * inv;
        u64 cc = pk2(ci, ci), ns = pk2(-si, si);
#pragma unroll
        for (int k = 0; k < 8; k++) {
            u64 tt = mul2(PA[k], cc);
            float lo, hi; upk2(PA[k], lo, hi);
            PA[k] = fma2(pk2(hi, lo), ns, tt);
        }
    }
#pragma unroll
    for (int p = 0; p < 3; p++) {                 // q8,q7,q6 ; m = 1,2,4
        float2 g = sg[8 - p];
        u64 cc = pk2(g.x, g.x), sp = pk2(g.y, g.y), sn = pk2(-g.y, -g.y);
        int m = 1 << p;
#pragma unroll
        for (int k = 0; k < 8; k++) if (!(k & m)) {
            u64 a = PA[k], bb = PA[k | m];
            PA[k]     = fma2(bb, sn, mul2(a, cc));
            PA[k | m] = fma2(a, sp, mul2(bb, cc));
        }
    }
#pragma unroll
    for (int d = 0; d < 2; d++) {                 // q5 (xor1), q4 (xor2)
        float2 g = sg[5 - d];
        int msk = 1 << d;
        float sgn = (lane & msk) ? g.y : -g.y;
        u64 cc = pk2(g.x, g.x), sv = pk2(sgn, sgn);
#pragma unroll
        for (int k = 0; k < 8; k++) {
            u64 pt = __shfl_xor_sync(0xffffffffu, PA[k], msk);
            PA[k] = fma2(pt, sv, mul2(PA[k], cc));
        }
    }

    // ---- T1: LA -> LB' (real floats) ---------------------------------------
    {
        int base = t * 16 + (t >> 1);             // addr(i)=i+(i>>5), i=t*16+ra
#pragma unroll
        for (int k = 0; k < 8; k++) {
            float lo, hi; upk2(PA[k], lo, hi);
            bufr[base + 2 * k]     = lo;
            bufr[base + 2 * k + 1] = hi;
        }
    }
    __syncthreads();
    u64 PB[8];
    {
        float v[16];
#pragma unroll
        for (int rb = 0; rb < 16; rb++) {
            int i = rb * 64 + lane * 2 + w;
            v[rb] = bufr[i + (i >> 5)];
        }
#pragma unroll
        for (int k = 0; k < 8; k++) PB[k] = pk2(v[2 * k], v[2 * k + 1]);
    }
    __syncthreads();

    // ---- stage A in LB': q3 in-pack, q2..q0 pack-pairs ---------------------
    {
        float2 g = sg[3];
        u64 cc = pk2(g.x, g.x), ns = pk2(-g.y, g.y);
#pragma unroll
        for (int k = 0; k < 8; k++) {
            u64 tt = mul2(PB[k], cc);
            float lo, hi; upk2(PB[k], lo, hi);
            PB[k] = fma2(pk2(hi, lo), ns, tt);
        }
    }
#pragma unroll
    for (int p = 0; p < 3; p++) {                 // q2,q1,q0 ; m = 1,2,4
        float2 g = sg[2 - p];
        u64 cc = pk2(g.x, g.x), sp = pk2(g.y, g.y), sn = pk2(-g.y, -g.y);
        int m = 1 << p;
#pragma unroll
        for (int k = 0; k < 8; k++) if (!(k & m)) {
            u64 a = PB[k], bb = PB[k | m];
            PB[k]     = fma2(bb, sn, mul2(a, cc));
            PB[k | m] = fma2(a, sp, mul2(bb, cc));
        }
    }

    // ---- C1: store LB', gather+PhA into LA (real -> complex) ---------------
#pragma unroll
    for (int k = 0; k < 8; k++) {
        float lo, hi; upk2(PB[k], lo, hi);
        int i0 = (2 * k) * 64 + lane * 2 + w;
        bufr[i0 + (i0 >> 5)] = lo;
        int i1 = i0 + 64;
        bufr[i1 + (i1 >> 5)] = hi;
    }
    __syncthreads();
    u64 P[16];
    {
        const u64* phA = (const u64*)d_phA;
#pragma unroll
        for (int ra = 0; ra < 16; ra++) {
            int i  = t * 16 + ra;
            int gi = (i ^ (i >> 1)) ^ ((i & 1) ? 0x300 : 0);
            float r = bufr[gi + (gi >> 5)];
            u64 ph = __ldg(&phA[ra * 64 + t]);
            P[ra] = mul2(pk2(r, r), ph);
        }
    }
    __syncthreads();

    // ---- stage B in LA (complex): q9..q6 reg, q5,q4 shfl -------------------
#pragma unroll
    for (int p = 0; p < 4; p++) {                 // q9,q8,q7,q6 ; m = 1,2,4,8
        float2 g = sg[10 + 9 - p];
        u64 cc = pk2(g.x, g.x), sp = pk2(g.y, g.y), sn = pk2(-g.y, -g.y);
        int m = 1 << p;
#pragma unroll
        for (int r = 0; r < 16; r++) if (!(r & m)) {
            u64 a = P[r], bb = P[r | m];
            P[r]     = fma2(bb, sn, mul2(a, cc));
            P[r | m] = fma2(a, sp, mul2(bb, cc));
        }
    }
#pragma unroll
    for (int d = 0; d < 2; d++) {                 // q5 (xor1), q4 (xor2)
        float2 g = sg[10 + 5 - d];
        int msk = 1 << d;
        float sgn = (lane & msk) ? g.y : -g.y;
        u64 cc = pk2(g.x, g.x), sv = pk2(sgn, sgn);
#pragma unroll
        for (int r = 0; r < 16; r++) {
            u64 pt = __shfl_xor_sync(0xffffffffu, P[r], msk);
            P[r] = fma2(pt, sv, mul2(P[r], cc));
        }
    }

    // ---- T2: LA -> LB' (complex u64) ---------------------------------------
#pragma unroll
    for (int ra = 0; ra < 16; ra++) {
        int i = t * 16 + ra;
        bufu[i + (i >> 5)] = P[ra];
    }
    __syncthreads();
#pragma unroll
    for (int rb = 0; rb < 16; rb++) {
        int i = rb * 64 + lane * 2 + w;
        P[rb] = bufu[i + (i >> 5)];
    }
    __syncthreads();

    // ---- stage B in LB' (complex): q3..q0 reg ------------------------------
#pragma unroll
    for (int p = 0; p < 4; p++) {                 // q3,q2,q1,q0 ; m = 1,2,4,8
        float2 g = sg[10 + 3 - p];
        u64 cc = pk2(g.x, g.x), sp = pk2(g.y, g.y), sn = pk2(-g.y, -g.y);
        int m = 1 << p;
#pragma unroll
        for (int r = 0; r < 16; r++) if (!(r & m)) {
            u64 a = P[r], bb = P[r | m];
            P[r]     = fma2(bb, sn, mul2(a, cc));
            P[r | m] = fma2(a, sp, mul2(bb, cc));
        }
    }

    // ---- C2: store LB', gather+PhB into LB' --------------------------------
#pragma unroll
    for (int rb = 0; rb < 16; rb++) {
        int i = rb * 64 + lane * 2 + w;
        bufu[i + (i >> 5)] = P[rb];
    }
    __syncthreads();
    {
        const u64* phB = (const u64*)d_phB;
#pragma unroll
        for (int rb = 0; rb < 16; rb++) {
            int i  = rb * 64 + lane * 2 + w;
            int gi = (i ^ (i >> 1)) ^ ((i & 1) ? 0x300 : 0);
            u64 v  = bufu[gi + (gi >> 5)];
            u64 ph = __ldg(&phB[rb * 64 + t]);
            float vx, vy, pr, pi;
            upk2(v, vx, vy); upk2(ph, pr, pi);
            P[rb] = pk2(vx * pr - vy * pi, vx * pi + vy * pr);
        }
    }

    // ---- Z expectations: Walsh tree over rb bits (q3..q0), lane signs ------
    float zq[6];
    {
        float s0[8]; float z3 = 0.0f;
#pragma unroll
        for (int k = 0; k < 8; k++) {
            u64 na = mul2(P[2 * k], P[2 * k]);
            u64 nb = mul2(P[2 * k + 1], P[2 * k + 1]);
            float al, ah, bl, bh; upk2(na, al, ah); upk2(nb, bl, bh);
            float a = al + ah, bq = bl + bh;
            s0[k] = a + bq;  z3 += a - bq;
        }
        float s1[4]; float z2 = 0.0f;
#pragma unroll
        for (int k = 0; k < 4; k++) { s1[k] = s0[2 * k] + s0[2 * k + 1]; z2 += s0[2 * k] - s0[2 * k + 1]; }
        float s2[2]; float z1 = 0.0f;
#pragma unroll
        for (int k = 0; k < 2; k++) { s2[k] = s1[2 * k] + s1[2 * k + 1]; z1 += s1[2 * k] - s1[2 * k + 1]; }
        float tot = s2[0] + s2[1];
        zq[0] = s2[0] - s2[1];
        zq[1] = z1; zq[2] = z2; zq[3] = z3;
        zq[4] = (lane & 16) ? -tot : tot;     // q4 = i5 = lane bit4
        zq[5] = (lane & 8)  ? -tot : tot;     // q5 = i4 = lane bit3
    }

    // ---- X/Y expectations ---------------------------------------------------
    float xr[6], yi[6];
#pragma unroll
    for (int q = 0; q < 4; q++) {                 // q0..q3: m = 8,4,2,1
        int m = 8 >> q;
        u64 acd = 0ull, acc = 0ull;
#pragma unroll
        for (int r = 0; r < 16; r++) if (!(r & m)) {
            u64 a = P[r], bp = P[r | m];
            acd = fma2(a, bp, acd);
            float bl, bh; upk2(bp, bl, bh);
            acc = fma2(a, pk2(bh, bl), acc);
        }
        float dl, dh, cl, ch; upk2(acd, dl, dh); upk2(acc, cl, ch);
        xr[q] = 2.0f * (dl + dh);
        yi[q] = 2.0f * (cl - ch);
    }
#pragma unroll
    for (int e = 0; e < 2; e++) {                 // q4 (xor16), q5 (xor8)
        int d = 16 >> e;
        u64 acd = 0ull, acc = 0ull;
#pragma unroll
        for (int r = 0; r < 16; r++) {
            u64 pt = __shfl_xor_sync(0xffffffffu, P[r], d);
            acd = fma2(P[r], pt, acd);
            float pl, ph2; upk2(pt, pl, ph2);
            acc = fma2(P[r], pk2(ph2, pl), acc);
        }
        float dl, dh, cl, ch; upk2(acd, dl, dh); upk2(acc, cl, ch);
        float yv = cl - ch;
        if (lane & d) yv = -yv;
        xr[4 + e] = dl + dh;                      // both halves counted
        yi[4 + e] = yv;
    }

#pragma unroll
    for (int q = 0; q < 6; q++) {
        xr[q] = wsum(xr[q]);
        yi[q] = wsum(yi[q]);
        zq[q] = wsum(zq[q]);
    }
    if (lane == 0) {
#pragma unroll
        for (int q = 0; q < 6; q++) {
            sacc[w * 18 + q]      = xr[q];
            sacc[w * 18 + 6 + q]  = yi[q];
            sacc[w * 18 + 12 + q] = zq[q];
        }
    }
    __syncthreads();
    if (t < 6) {
        int q = t;
        float X = sacc[q]      + sacc[18 + q];
        float Y = sacc[6 + q]  + sacc[24 + q];
        float Z = sacc[12 + q] + sacc[30 + q];
        float2 g = sg[20 + q];
        float* o = out + (size_t)b * 18;
        o[q]      = g.x * X + g.y * Z;
        o[6 + q]  = Y;
        o[12 + q] = g.x * Z - g.y * X;
    }
}

extern "C" void kernel_launch(void* const* d_in, const int* in_sizes, int n_in,
                              void* d_out, int out_size)
{
    int ix = 0, iw = 1;
    if (n_in >= 2 && in_sizes[0] < in_sizes[1]) { ix = 1; iw = 0; }
    const float* x = (const float*)d_in[ix];
    const float* w = (const float*)d_in[iw];
    float* out = (float*)d_out;

    int B = out_size / 18;
    int D = (B > 0) ? (in_sizes[ix] / B) : 0;

    qae_setup<<<1, 1024>>>(w);
    qae9_kernel<<<B, NT>>>(x, out, B, D);
}

// round 10
// speedup vs baseline: 1.5689x; 1.1926x over previous
#include <cuda_runtime.h>

// QAEEncoder R10: R6 pipeline, but the final CNOT permutation + RZ phase (C2)
// are folded into the measured operators (Pauli pushback) - no C2 pass at all.
// Layouts over amp index j[9:0] (qubit q <-> bit p=9-q):
//   L1: lane=j[9:5], reg=j[4:0]     L0: lane=j[4:0], reg r=j[9:5]
// Pipeline:
//   load+norm (L1, real, packed; norm folded into first gate)
//   -> A gates q9..5 (L1 regs, f32x2) -> T_A (L1->L0) -> A gates q4..0 (L0)
//   -> C1 gather+PhA (->L1 complex) -> B gates q9..5 (L1) -> T_B (L1->L0)
//   -> B gates q4..0 (L0) -> measure with (PhB . Perm)-conjugated operators;
//   stage-C RY folded; qubits 6-9 traced out.
// CNOT-ring: new[i]=old[g(i)], g(i)=(i^(i>>1))^((i&1)?0x300:0).
// g^{-1}: i_p(j)=parity(j & M_p), M_p = bits p..9 (p=1..8); i9: j&0x1FF; i0: parity(j).
// X_q/Y_q pushback: pairs (j, j^Delta_p), Delta_p = g(e_p) = bits {p-1,p};
//   phase delta = v_{p-1}(1-2 j_{p-1}) + v_p(1-2 j_p), v_k = w[40+9-k].

constexpr int SPB = 4;               // states (warps) per block
constexpr int NT  = 32 * SPB;
using u64 = unsigned long long;

__device__ float2 d_phA[1024];   // transposed: dest i at [(i&31)*32 + (i>>5)]
__device__ float2 d_g[33];       // [0,20)=gAB, [20,26)=gC, [26,33)=E_m=exp(i w[40+m])

__device__ __forceinline__ u64 pk2(float a, float b) {
    u64 r; asm("mov.b64 %0,{%1,%2};" : "=l"(r) : "f"(a), "f"(b)); return r;
}
__device__ __forceinline__ void upk2(u64 v, float& a, float& b) {
    asm("mov.b64 {%0,%1},%2;" : "=f"(a), "=f"(b) : "l"(v));
}
__device__ __forceinline__ u64 mul2(u64 a, u64 b) {
    u64 d; asm("mul.rn.f32x2 %0,%1,%2;" : "=l"(d) : "l"(a), "l"(b)); return d;
}
__device__ __forceinline__ u64 fma2(u64 a, u64 b, u64 c) {
    u64 d; asm("fma.rn.f32x2 %0,%1,%2,%3;" : "=l"(d) : "l"(a), "l"(b), "l"(c)); return d;
}
__device__ __forceinline__ float wsum(float v) {
#pragma unroll
    for (int o = 16; o; o >>= 1) v += __shfl_xor_sync(0xffffffffu, v, o);
    return v;
}

// ---- setup ------------------------------------------------------------------
__global__ void qae_setup(const float* __restrict__ w)
{
    int t = threadIdx.x;   // 1024 threads
    {
        int gi = (t ^ (t >> 1)) ^ ((t & 1) ? 0x300 : 0);
        float phA = 0.0f;
#pragma unroll
        for (int p = 0; p < 10; p++)
            phA += w[10 + 9 - p] * (((gi >> p) & 1) ? 0.5f : -0.5f);
        float c, s;
        sincosf(phA, &s, &c);
        d_phA[(t & 31) * 32 + (t >> 5)] = make_float2(c, s);
    }
    if (t < 20) {
        int st = t / 10, q = t % 10;
        float th = st ? (w[20 + q] + w[30 + q]) : w[q];
        float c, s; sincosf(0.5f * th, &s, &c);
        d_g[t] = make_float2(c, s);
    } else if (t < 26) {
        float c, s; sincosf(w[50 + (t - 20)], &s, &c);
        d_g[t] = make_float2(c, s);
    } else if (t < 33) {
        float c, s; sincosf(w[40 + (t - 26)], &s, &c);
        d_g[t] = make_float2(c, s);
    }
}

__global__ void __launch_bounds__(NT, 6)
qae10_kernel(const float* __restrict__ x,
             float* __restrict__ out,
             int B, int D)
{
    __shared__ u64    sbuf[SPB][33 * 32];   // staging: float stride 34 / u64 stride 33
    __shared__ float2 sg[33];

    const int tid  = threadIdx.x;
    const int wid  = tid >> 5;
    const int lane = tid & 31;
    const int b    = blockIdx.x * SPB + wid;

    if (tid < 33) sg[tid] = d_g[tid];
    __syncthreads();
    if (b >= B) return;                 // warps independent from here

    float* bufr = (float*)sbuf[wid];    // stride-34 float view (T_A / C1)
    u64*   bufu = sbuf[wid];            // stride-33 u64 view   (T_B)

    // ---- load (L1, real, packed over qubit-9 pairs) ------------------------
    u64 PA[16];
    float ss = 0.0f;
    const float* xrow = x + (size_t)b * D + lane * 32;
    if ((lane + 1) * 32 <= D) {
#pragma unroll
        for (int t = 0; t < 8; t++) {
            float4 v = *(const float4*)(xrow + t * 4);
            PA[2 * t]     = pk2(v.x, v.y);
            PA[2 * t + 1] = pk2(v.z, v.w);
            ss += v.x * v.x + v.y * v.y + v.z * v.z + v.w * v.w;
        }
    } else {
#pragma unroll
        for (int t = 0; t < 8; t++) {
            int idx = lane * 32 + t * 4;
            float4 v;
            v.x = (idx     < D) ? xrow[t * 4]     : 0.0f;
            v.y = (idx + 1 < D) ? xrow[t * 4 + 1] : 0.0f;
            v.z = (idx + 2 < D) ? xrow[t * 4 + 2] : 0.0f;
            v.w = (idx + 3 < D) ? xrow[t * 4 + 3] : 0.0f;
            PA[2 * t]     = pk2(v.x, v.y);
            PA[2 * t + 1] = pk2(v.z, v.w);
            ss += v.x * v.x + v.y * v.y + v.z * v.z + v.w * v.w;
        }
    }
    ss = wsum(ss);
    float inv = 1.0f / fmaxf(sqrtf(ss), 1e-8f);

    // ---- stage A, qubits 9..5 (L1 reg bits; qubit 9 in-pack, norm folded) --
    {
        float2 g = sg[9];
        float ci = g.x * inv, si = g.y * inv;
        u64 cc = pk2(ci, ci), ns = pk2(-si, si);
#pragma unroll
        for (int k = 0; k < 16; k++) {
            u64 t = mul2(PA[k], cc);
            float lo, hi; upk2(PA[k], lo, hi);
            PA[k] = fma2(pk2(hi, lo), ns, t);
        }
    }
#pragma unroll
    for (int p = 1; p < 5; p++) {
        float2 g = sg[9 - p];
        u64 cc = pk2(g.x, g.x), sp = pk2(g.y, g.y), sn = pk2(-g.y, -g.y);
        int m = 1 << (p - 1);
#pragma unroll
        for (int k = 0; k < 16; k++) if (!(k & m)) {
            u64 a = PA[k], bb = PA[k | m];
            PA[k]     = fma2(bb, sn, mul2(a, cc));
            PA[k | m] = fma2(a, sp, mul2(bb, cc));
        }
    }

    // ---- T_A: L1 -> L0. addr(i) = i[9:5]*34 + i[4:0] -----------------------
#pragma unroll
    for (int k = 0; k < 16; k++) bufu[lane * 17 + k] = PA[k];
    __syncwarp();
    u64 PB[16];
#pragma unroll
    for (int k = 0; k < 16; k++)
        PB[k] = pk2(bufr[(2 * k) * 34 + lane], bufr[(2 * k + 1) * 34 + lane]);
    __syncwarp();

    // ---- stage A, qubits 4..0 (L0 reg bits; qubit 4 in-pack) ---------------
    {
        float2 g = sg[4];
        u64 cc = pk2(g.x, g.x), ns = pk2(-g.y, g.y);
#pragma unroll
        for (int k = 0; k < 16; k++) {
            u64 t = mul2(PB[k], cc);
            float lo, hi; upk2(PB[k], lo, hi);
            PB[k] = fma2(pk2(hi, lo), ns, t);
        }
    }
#pragma unroll
    for (int p = 1; p < 5; p++) {
        float2 g = sg[4 - p];
        u64 cc = pk2(g.x, g.x), sp = pk2(g.y, g.y), sn = pk2(-g.y, -g.y);
        int m = 1 << (p - 1);
#pragma unroll
        for (int k = 0; k < 16; k++) if (!(k & m)) {
            u64 a = PB[k], bb = PB[k | m];
            PB[k]     = fma2(bb, sn, mul2(a, cc));
            PB[k | m] = fma2(a, sp, mul2(bb, cc));
        }
    }

    // ---- C1: CNOT gather + PhA (store L0, read into L1, -> complex) --------
    u64 P[32];
    {
#pragma unroll
        for (int k = 0; k < 16; k++) {
            float lo, hi; upk2(PB[k], lo, hi);
            bufr[(2 * k) * 34 + lane]     = lo;
            bufr[(2 * k + 1) * 34 + lane] = hi;
        }
        __syncwarp();
        const u64* phA = (const u64*)d_phA;
#pragma unroll
        for (int j = 0; j < 32; j++) {  // output L1: lane=i[9:5], j=i[4:0]
            int i  = (lane << 5) | j;
            int gi = (i ^ (i >> 1)) ^ ((j & 1) ? 0x300 : 0);
            float r = bufr[(gi >> 5) * 34 + (gi & 31)];
            u64 ph = __ldg(&phA[j * 32 + lane]);
            P[j] = mul2(pk2(r, r), ph);
        }
        __syncwarp();
    }

    // ---- stage B, qubits 9..5 (L1 reg bits, complex f32x2) -----------------
#pragma unroll
    for (int bl = 0; bl < 5; bl++) {
        float2 g = sg[10 + 9 - bl];
        u64 cc = pk2(g.x, g.x), sp = pk2(g.y, g.y), sn = pk2(-g.y, -g.y);
        int m = 1 << bl;
#pragma unroll
        for (int j = 0; j < 32; j++) if (!(j & m)) {
            u64 a = P[j], bb = P[j | m];
            P[j]     = fma2(bb, sn, mul2(a, cc));
            P[j | m] = fma2(a, sp, mul2(bb, cc));
        }
    }

    // ---- T_B: L1 -> L0 (u64 transpose, stride 33) --------------------------
#pragma unroll
    for (int j = 0; j < 32; j++) bufu[lane * 33 + j] = P[j];
    __syncwarp();
#pragma unroll
    for (int j = 0; j < 32; j++) P[j] = bufu[j * 33 + lane];

    // ---- stage B, qubits 4..0 (L0 reg bits) --------------------------------
#pragma unroll
    for (int bl = 0; bl < 5; bl++) {
        float2 g = sg[10 + 4 - bl];
        u64 cc = pk2(g.x, g.x), sp = pk2(g.y, g.y), sn = pk2(-g.y, -g.y);
        int m = 1 << bl;
#pragma unroll
        for (int j = 0; j < 32; j++) if (!(j & m)) {
            u64 a = P[j], bb = P[j | m];
            P[j]     = fma2(bb, sn, mul2(a, cc));
            P[j | m] = fma2(a, sp, mul2(bb, cc));
        }
    }

    // ======= measurement with (PhB . Perm) pushed into the operators ========
    // L0: lane = j[4:0], reg r = j[9:5].
    const int lanepar = __popc(lane) & 1;
    const int lane4   = (lane >> 4) & 1;
    const int lane3   = (lane >> 3) & 1;

    // ---- Z: Walsh coefficients at masks M_p (reg part compile-time) --------
    float zA = 0, zB = 0, zC = 0, zD = 0, zE = 0;
#pragma unroll
    for (int r = 0; r < 32; r++) {
        u64 s = mul2(P[r], P[r]);
        float lo, hi; upk2(s, lo, hi);
        float nv = lo + hi;
        zA = (__popc(r & 0x0F) & 1) ? zA - nv : zA + nv;
        zB = (__popc(r & 0x18) & 1) ? zB - nv : zB + nv;
        zC = (__popc(r & 0x1C) & 1) ? zC - nv : zC + nv;
        zD = (__popc(r & 0x1E) & 1) ? zD - nv : zD + nv;
        zE = (__popc(r & 0x1F) & 1) ? zE - nv : zE + nv;
    }
    float zq[6];
    zq[0] = lanepar ? -zA : zA;
    zq[1] = zB; zq[2] = zC; zq[3] = zD; zq[4] = zE;
    zq[5] = lane4 ? -zE : zE;

    // ---- X/Y: q=0..3 (reg-pairs, Delta in r-bits), 4 phase buckets ---------
    float ReS[6], ImS[6];
    {
        const int DR[4] = {0x18, 0x0C, 0x06, 0x03};   // Delta (r part)
        const int KM[4] = {0x0F, 0x18, 0x1C, 0x1E};   // key mask (r part)
        const int BA[4] = {3, 2, 1, 0};               // r-bit of phase-bit a=p-1
#pragma unroll
        for (int q = 0; q < 4; q++) {
            const int dr = DR[q], low = dr & (-dr);
            u64 d0=0ull,d1=0ull,d2=0ull,d3=0ull, c0=0ull,c1=0ull,c2=0ull,c3=0ull;
#pragma unroll
            for (int r = 0; r < 32; r++) if (!(r & low)) {
                int k  = __popc(r & KM[q]) & 1;       // q=0: fixed convention
                int ra = k ? (r ^ dr) : r;
                u64 a = P[ra], bb = P[ra ^ dr];
                float bl, bh; upk2(bb, bl, bh);
                u64 bs = pk2(bh, bl);
                int bkt = (((ra >> BA[q]) & 1) << 1) | ((ra >> (BA[q] + 1)) & 1);
                if      (bkt == 0) { d0 = fma2(a, bb, d0); c0 = fma2(a, bs, c0); }
                else if (bkt == 1) { d1 = fma2(a, bb, d1); c1 = fma2(a, bs, c1); }
                else if (bkt == 2) { d2 = fma2(a, bb, d2); c2 = fma2(a, bs, c2); }
                else               { d3 = fma2(a, bb, d3); c3 = fma2(a, bs, c3); }
            }
            float2 Eb = sg[26 + q], Ea = sg[26 + q + 1];
            float Re = 0.0f, Im = 0.0f;
            u64 AD[4] = {d0, d1, d2, d3}, AC[4] = {c0, c1, c2, c3};
#pragma unroll
            for (int t = 0; t < 4; t++) {
                int ja = (t >> 1) & 1, jb = t & 1;
                float sa = ja ? -Ea.y : Ea.y;
                float sb = jb ? -Eb.y : Eb.y;
                float cosd = Ea.x * Eb.x - sa * sb;
                float sind = sa * Eb.x + sb * Ea.x;
                float dl, dh, cl, ch; upk2(AD[t], dl, dh); upk2(AC[t], cl, ch);
                float Rb = dl + dh, Ib = cl - ch;
                Re += Rb * cosd - Ib * sind;
                Im += Rb * sind + Ib * cosd;
            }
            ReS[q] = Re;
            ImS[q] = (q == 0 && lanepar) ? -Im : Im;  // conj for odd-parity lanes
        }
    }
    // ---- q=4: pairs (r, r^1) x (lane, lane^16); key = parity(r)=0 ----------
    {
        u64 dE=0ull, cE=0ull, dO=0ull, cO=0ull;       // buckets by r0 of included side
#pragma unroll
        for (int r = 0; r < 32; r++) if (!(__popc(r) & 1)) {
            u64 bb = __shfl_xor_sync(0xffffffffu, P[r ^ 1], 16);
            float bl, bh; upk2(bb, bl, bh);
            u64 bs = pk2(bh, bl);
            if (r & 1) { dO = fma2(P[r], bb, dO); cO = fma2(P[r], bs, cO); }
            else       { dE = fma2(P[r], bb, dE); cE = fma2(P[r], bs, cE); }
        }
        float dl, dh, cl, ch;
        upk2(dE, dl, dh); upk2(cE, cl, ch);
        float ReE = dl + dh, ImE = cl - ch;
        upk2(dO, dl, dh); upk2(cO, cl, ch);
        float ReO = dl + dh, ImO = cl - ch;
        float2 E5 = sg[30];                            // bit5 weight w[44]
        float Re = (ReE * E5.x - ImE * E5.y) + (ReO * E5.x + ImO * E5.y);
        float Im = (ReE * E5.y + ImE * E5.x) + (ImO * E5.x - ReO * E5.y);
        float2 E4 = sg[31];                            // bit4 weight w[45]
        float c4 = E4.x, s4 = lane4 ? -E4.y : E4.y;
        ReS[4] = Re * c4 - Im * s4;
        ImS[4] = Re * s4 + Im * c4;
    }
    // ---- q=5: pairs (lane, lane^24); key = parity(r)^lane4 -----------------
    {
        u64 dE=0ull, cE=0ull, dO=0ull, cO=0ull;       // buckets by parity(r)
#pragma unroll
        for (int r = 0; r < 32; r++) {
            u64 bb = __shfl_xor_sync(0xffffffffu, P[r], 24);
            float bl, bh; upk2(bb, bl, bh);
            u64 bs = pk2(bh, bl);
            if (__popc(r) & 1) { dO = fma2(P[r], bb, dO); cO = fma2(P[r], bs, cO); }
            else               { dE = fma2(P[r], bb, dE); cE = fma2(P[r], bs, cE); }
        }
        u64 ad = lane4 ? dO : dE;
        u64 ac = lane4 ? cO : cE;
        float dl, dh, cl, ch; upk2(ad, dl, dh); upk2(ac, cl, ch);
        float Re = dl + dh, Im = cl - ch;
        float2 E3 = sg[32];                            // bit3 weight w[46]
        float2 E4 = sg[31];                            // bit4 weight w[45]
        float s3 = lane3 ? -E3.y : E3.y;
        float s4 = lane4 ? -E4.y : E4.y;
        float cosd = E3.x * E4.x - s3 * s4;
        float sind = s3 * E4.x + s4 * E3.x;
        ReS[5] = Re * cosd - Im * sind;
        ImS[5] = Re * sind + Im * cosd;
    }

#pragma unroll
    for (int q = 0; q < 6; q++) {
        ReS[q] = wsum(ReS[q]);
        ImS[q] = wsum(ImS[q]);
        zq[q]  = wsum(zq[q]);
    }

    if (lane == 0) {
        float* o = out + (size_t)b * 18;
#pragma unroll
        for (int q = 0; q < 6; q++) {
            float X = 2.0f * ReS[q], Y = 2.0f * ImS[q];
            float2 gc = sg[20 + q];
            o[q]      = gc.x * X + gc.y * zq[q];
            o[6 + q]  = Y;
            o[12 + q] = gc.x * zq[q] - gc.y * X;
        }
    }
}

extern "C" void kernel_launch(void* const* d_in, const int* in_sizes, int n_in,
                              void* d_out, int out_size)
{
    int ix = 0, iw = 1;
    if (n_in >= 2 && in_sizes[0] < in_sizes[1]) { ix = 1; iw = 0; }
    const float* x = (const float*)d_in[ix];
    const float* w = (const float*)d_in[iw];
    float* out = (float*)d_out;

    int B = out_size / 18;
    int D = (B > 0) ? (in_sizes[ix] / B) : 0;

    qae_setup<<<1, 1024>>>(w);
    int grid = (B + SPB - 1) / SPB;
    qae10_kernel<<<grid, NT>>>(x, out, B, D);
}